// round 16
// baseline (speedup 1.0000x reference)
#include <cuda_runtime.h>
#include <cuda_fp16.h>
#include <cstdint>
#include <math.h>

// ---------------- problem constants ----------------
#define B_  8
#define S_  2048
#define D_  1024
#define H_  1024
#define M_  (B_*S_)        // 16384
#define N2_ 2048           // interleaved (k,ph) output width
#define NC_ 16             // chunks per sequence (S_/BM)
#define NCHAIN_ 128        // chains per layer: 16 h-tiles x 8 batches
#define LSTRIDE (NCHAIN_ * NC_)   // 2048 lookback slots per layer

// ---------------- scratch ----------------
__device__ __half  g_Xh [(size_t)M_ * D_];       // fp16 K-perm32 layer-0 input
__device__ __half  g_X2 [(size_t)M_ * D_];       // fp16 K-perm32 layer-1 input
__device__ __half  g_Wc [2 * (size_t)N2_ * D_];  // both layers, interleaved+perm32
__device__ int     g_status[2 * LSTRIDE];
__device__ float2  g_agg   [2 * LSTRIDE * 64];
__device__ int     g_rowcnt[NCHAIN_];            // layer-0 -> layer-1 row readiness

// ---------------- helpers ----------------
__device__ __forceinline__ uint32_t h2_as_u32(__half2 h) {
    union { __half2 h; uint32_t u; } cvt; cvt.h = h; return cvt.u;
}
__device__ __forceinline__ uint32_t smem_u32(const void* p) {
    uint32_t a;
    asm("{ .reg .u64 t; cvta.to.shared.u64 t, %1; cvt.u32.u64 %0, t; }" : "=r"(a) : "l"(p));
    return a;
}
__device__ __forceinline__ void cpasync16(uint32_t dst, const void* src) {
    asm volatile("cp.async.cg.shared.global [%0], [%1], 16;" :: "r"(dst), "l"(src));
}
#define CP_COMMIT() asm volatile("cp.async.commit_group;" ::: "memory")
#define CP_WAIT0()  asm volatile("cp.async.wait_group 0;" ::: "memory")

__device__ __forceinline__ void mma_fp16(float* c,
    uint32_t a0, uint32_t a1, uint32_t a2, uint32_t a3, uint32_t b0, uint32_t b1)
{
    asm volatile(
        "mma.sync.aligned.m16n8k16.row.col.f32.f16.f16.f32 "
        "{%0,%1,%2,%3}, {%4,%5,%6,%7}, {%8,%9}, {%0,%1,%2,%3};"
        : "+f"(c[0]), "+f"(c[1]), "+f"(c[2]), "+f"(c[3])
        : "r"(a0), "r"(a1), "r"(a2), "r"(a3), "r"(b0), "r"(b1));
}

// one-exp gates: t=e^kv -> a=sigmoid(-kv)=1/(1+t), z=sigmoid(kv)=t/(1+t)
__device__ __forceinline__ void gates2(float kv, float ph, float& a, float& b) {
    float t = __expf(fminf(kv, 80.f));
    float r = __fdividef(1.f, 1.f + t);
    a = r;
    float z = t * r;
    float g = (ph >= 0.f) ? (ph + 0.5f)
                          : __fdividef(1.f, 1.f + __expf(-ph));
    b = z * g;
}

// K-perm32: within each 32-k block, dst uint4[t] = {pair(t), pair(t+4),
// pair(t+8), pair(t+12)} so one LDS.128 yields fragments of BOTH k16 groups.
__device__ __forceinline__ void perm32(const float4* __restrict__ s, uint4* o) {
    #pragma unroll
    for (int t = 0; t < 4; t++) {
        uint32_t r[4];
        #pragma unroll
        for (int j = 0; j < 4; j++) {
            int p = t + 4 * j;                 // source pair index (k=2p,2p+1)
            float4 v = s[p >> 1];
            float lo = (p & 1) ? v.z : v.x;
            float hi = (p & 1) ? v.w : v.y;
            r[j] = h2_as_u32(__floats2half2_rn(lo, hi));
        }
        o[t] = make_uint4(r[0], r[1], r[2], r[3]);
    }
}
// permuted column index for a single h within its 32-group
__device__ __forceinline__ int permcol32(int h) {
    int p = (h & 31) >> 1, r = h & 1;
    return (h & ~31) | (((p & 3) * 8 + (p >> 2) * 2) | r);
}

// ---------------- prep: status/rowcnt zero + X convert + W interleave ----------
#define NX32 ((int)((size_t)M_ * D_ / 32))        // 524288
#define NW32 ((int)(2 * (size_t)H_ * D_ / 32))    // 65536
__global__ __launch_bounds__(256) void prep_kernel(
    const float4* __restrict__ x,
    const float4* __restrict__ Wz, const float4* __restrict__ Wh,
    uint4* __restrict__ Xh, uint4* __restrict__ Wc,
    int* __restrict__ st, int* __restrict__ rowcnt)
{
    int i = blockIdx.x * 256 + threadIdx.x;
    if (i < 2 * LSTRIDE) st[i] = 0;
    if (i < NCHAIN_) rowcnt[i] = 0;
    if (i < NX32) {
        float4 s[8];
        #pragma unroll
        for (int j = 0; j < 8; j++) s[j] = x[8*i + j];
        uint4 o[4];
        perm32(s, o);
        #pragma unroll
        for (int j = 0; j < 4; j++) Xh[4*i + j] = o[j];
    } else {
        int j = i - NX32;
        if (j >= NW32) return;
        int l = j >> 15;                          // layer
        int jj = j & 32767;
        int h = jj >> 5, sgp = jj & 31;           // D/32 = 32 groups per row
        const float4* wz = Wz + (size_t)l * (H_ * D_ / 4) + (size_t)jj * 8;
        const float4* wh = Wh + (size_t)l * (H_ * D_ / 4) + (size_t)jj * 8;
        float4 sz[8], sh[8];
        #pragma unroll
        for (int q = 0; q < 8; q++) { sz[q] = wz[q]; sh[q] = wh[q]; }
        uint4 oz[4], oh[4];
        perm32(sz, oz);
        perm32(sh, oh);
        uint4* base = Wc + (size_t)l * (N2_ * D_ / 8);
        uint4* rz = base + (size_t)(2*h)   * 128 + sgp * 4;
        uint4* rh = base + (size_t)(2*h+1) * 128 + sgp * 4;
        #pragma unroll
        for (int q = 0; q < 4; q++) { rz[q] = oz[q]; rh[q] = oh[q]; }
    }
}

// ============================================================================
// Single-launch dual-layer fused GEMM + gates + chunk scan + output
// tile 128x128, 8 warps, warptile 64x32, BK=64, 2-stage, 2 blk/SM
// LDS.128 fragment loads via K-perm32; ST=96 (12 units/row -> conflict-free)
// ============================================================================
#define BM 128
#define BN 128
#define BK 64
#define NT 256
#define ST 96                            // halfs/row: 12x16B units; {g*12+t} mod 8 distinct
#define B_OFF (BM * ST)
#define STG_HALFS ((BM + BN) * ST)       // 24576
#define STG_BYTES (STG_HALFS * 2)        // 49152
#define GEMM_SMEM (2 * STG_BYTES)        // 98304
#define GST 136                          // gate tile row stride (floats)

// issue one stage of cp.async (A+B) from loop-carried pointers, then advance
__device__ __forceinline__ void issue_stage(
    uint32_t wA, uint32_t wB, const __half*& ap, const __half*& bp)
{
    #pragma unroll
    for (int i = 0; i < 4; i++)
        cpasync16(wA + (uint32_t)(i * 32 * ST) * 2, ap + (size_t)(i * 32) * D_);
    #pragma unroll
    for (int i = 0; i < 4; i++)
        cpasync16(wB + (uint32_t)(i * 32 * ST) * 2, bp + (size_t)(i * 32) * D_);
    CP_COMMIT();
    ap += BK; bp += BK;
}

// one pipeline step: wait current, prefetch into other, compute current
__device__ __forceinline__ void pipe_step(
    const __half* As, uint32_t wA_other, uint32_t wB_other,
    const __half*& ap, const __half*& bp, bool do_load,
    float c[4][4][4], int wm, int wn, int g, int tg8)
{
    CP_WAIT0();
    __syncthreads();
    if (do_load) issue_stage(wA_other, wB_other, ap, bp);

    const __half* Bs = As + B_OFF;
    #pragma unroll
    for (int blk = 0; blk < 2; blk++) {           // 2 x 32-k blocks per BK=64
        const int kb = blk * 32 + tg8;
        uint4 alo[4], ahi[4], bf[4];
        #pragma unroll
        for (int mt = 0; mt < 4; mt++) {
            const int m = wm + mt * 16 + g;
            alo[mt] = *(const uint4*)&As[m * ST + kb];        // a0,a2 of kg0|kg1
            ahi[mt] = *(const uint4*)&As[(m + 8) * ST + kb];  // a1,a3 of kg0|kg1
        }
        #pragma unroll
        for (int nt = 0; nt < 4; nt++) {
            const int n = wn + nt * 8 + g;
            bf[nt] = *(const uint4*)&Bs[n * ST + kb];         // b0,b1 of kg0|kg1
        }
        #pragma unroll
        for (int mt = 0; mt < 4; mt++)
            #pragma unroll
            for (int nt = 0; nt < 4; nt++) {
                mma_fp16(c[mt][nt], alo[mt].x, ahi[mt].x, alo[mt].y, ahi[mt].y,
                         bf[nt].x, bf[nt].y);
                mma_fp16(c[mt][nt], alo[mt].z, ahi[mt].z, alo[mt].w, ahi[mt].w,
                         bf[nt].z, bf[nt].w);
            }
    }
}

__global__ __launch_bounds__(NT, 2) void gemm_fused_kernel(
    const __half* __restrict__ Xh, const __half* __restrict__ X2g,
    const __half* __restrict__ Wc,
    const float* __restrict__ bz, const float* __restrict__ bh,
    int* __restrict__ status, float2* __restrict__ agg,
    int* __restrict__ rowcnt,
    __half* __restrict__ outH, float* __restrict__ outF)
{
    extern __shared__ __align__(16) char smraw[];
    __half* sm = (__half*)smraw;
    const uint32_t sb = smem_u32(sm);
    const int tid = threadIdx.x;
    const int lane = tid & 31, wid = tid >> 5;
    const int g = lane >> 2, tg = lane & 3;
    const int tg8 = 8 * tg;
    const int wm = (wid >> 2) * 64;
    const int wn = (wid & 3) * 32;
    const int bid = blockIdx.x;
    const int layer = bid >> 11;
    const int rem = bid & 2047;
    const int by = rem >> 4;
    const int bx = rem & 15;
    const int bm = by * BM;
    const int bn = bx * BN;

    const __half* Xin = layer ? X2g : Xh;
    const int lr = tid >> 3, lc = (tid & 7) << 3;
    const __half* ap = Xin + (size_t)(bm + lr) * D_ + lc;
    const __half* bp = Wc + (size_t)layer * (N2_ * D_) + (size_t)(bn + lr) * D_ + lc;
    const uint32_t wbase = (uint32_t)(lr * ST + lc) * 2;
    const uint32_t wA0 = sb + wbase,              wA1 = wA0 + STG_BYTES;
    const uint32_t wB0 = sb + B_OFF * 2 + wbase,  wB1 = wB0 + STG_BYTES;
    const __half* As0 = sm;
    const __half* As1 = sm + STG_HALFS;

    const float* bzp = bz + layer * H_;
    const float* bhp = bh + layer * H_;
    int*    stp  = status + layer * LSTRIDE;
    float2* aggp = agg + (size_t)layer * LSTRIDE * 64;

    float c[4][4][4];
    #pragma unroll
    for (int mt = 0; mt < 4; mt++)
        #pragma unroll
        for (int nt = 0; nt < 4; nt++)
            #pragma unroll
            for (int r = 0; r < 4; r++) c[mt][nt][r] = 0.f;

    if (layer == 1) {
        if (tid == 0)
            while (*(volatile int*)(rowcnt + by) < 16) __nanosleep(64);
        __syncthreads();
        __threadfence();
    }
    issue_stage(wA0, wB0, ap, bp);

    #pragma unroll 1
    for (int it = 0; it < 8; it++) {
        pipe_step(As0, wA1, wB1, ap, bp, true,   c, wm, wn, g, tg8);
        pipe_step(As1, wA0, wB0, ap, bp, it < 7, c, wm, wn, g, tg8);
    }

    // ---------- epilogue: gates -> interleaved smem tile sg[t][2h|2h+1] ----------
    __syncthreads();
    float* sg   = (float*)smraw;
    float* segA = sg + BM * GST;
    float* segB = segA + 256;
    float* shst = segB + 256;

    const int hbase = bn >> 1;
    #pragma unroll
    for (int nt = 0; nt < 4; nt++) {
        const int hl = (wn >> 1) + nt * 4 + tg;
        const float bzv = bzp[hbase + hl], bhv = bhp[hbase + hl];
        #pragma unroll
        for (int mt = 0; mt < 4; mt++) {
            const int t0 = wm + mt * 16 + g;
            float a0, b0, a1, b1;
            gates2(c[mt][nt][0] + bzv, c[mt][nt][1] + bhv, a0, b0);
            gates2(c[mt][nt][2] + bzv, c[mt][nt][3] + bhv, a1, b1);
            *(float2*)&sg[t0 * GST + 2 * hl]       = make_float2(a0, b0);
            *(float2*)&sg[(t0 + 8) * GST + 2 * hl] = make_float2(a1, b1);
        }
    }
    __syncthreads();

    // ---------- segment compose: 4 threads/column, 32 steps each ----------
    const int batch = by >> 4;
    const int chunk = by & 15;
    const int chain = bx * B_ + batch;
    const int sidx  = chain * NC_ + chunk;

    const int col = tid & 63;
    const int seg = tid >> 6;
    const int tseg = seg * 32;

    {
        float A = 1.f, Bv = 0.f;
        #pragma unroll 4
        for (int t = 0; t < 32; t++) {
            float2 v = *(const float2*)&sg[(tseg + t) * GST + 2 * col];
            Bv = fmaf(v.x, Bv, v.y);
            A *= v.x;
        }
        segA[seg * 64 + col] = A;
        segB[seg * 64 + col] = Bv;
    }
    __syncthreads();

    if (seg == 0) {
        float Ac = segA[col], Bc = segB[col];
        #pragma unroll
        for (int s = 1; s < 4; s++) {
            float As_ = segA[s * 64 + col], Bs_ = segB[s * 64 + col];
            Bc = fmaf(As_, Bc, Bs_);
            Ac *= As_;
        }
        aggp[(size_t)sidx * 64 + col] = make_float2(Ac, Bc);
        __threadfence();
    }
    __syncthreads();
    if (tid == 0) atomicExch(&stp[sidx], 1);

    if (seg == 0) {
        float Ar = 1.f, Br = 0.f;
        for (int p = chunk - 1; p >= 0; p--) {
            const int pidx = chain * NC_ + p;
            while (*(volatile int*)(stp + pidx) == 0) __nanosleep(32);
            __threadfence();
            float2 ab = aggp[(size_t)pidx * 64 + col];
            Br = fmaf(Ar, ab.y, Br);
            Ar *= ab.x;
        }
        shst[col] = fmaf(Ar, 0.5f, Br);
    }
    __syncthreads();

    {
        float h = shst[col];
        #pragma unroll
        for (int s = 0; s < 4; s++)
            if (s < seg) h = fmaf(segA[s * 64 + col], h, segB[s * 64 + col]);

        if (layer == 0) {
            const int hp = permcol32(hbase + col);
            __half* po = outH + (size_t)(bm + tseg) * H_ + hp;
            #pragma unroll 4
            for (int t = 0; t < 32; t++) {
                float2 v = *(const float2*)&sg[(tseg + t) * GST + 2 * col];
                h = fmaf(v.x, h, v.y);
                po[(size_t)t * H_] = __float2half_rn(h);
            }
        } else {
            float* po = outF + (size_t)(bm + tseg) * H_ + hbase + col;
            #pragma unroll 4
            for (int t = 0; t < 32; t++) {
                float2 v = *(const float2*)&sg[(tseg + t) * GST + 2 * col];
                h = fmaf(v.x, h, v.y);
                po[(size_t)t * H_] = h;
            }
        }
    }

    if (layer == 0) {
        __syncthreads();
        if (tid == 0) {
            __threadfence();
            atomicAdd(&rowcnt[by], 1);
        }
    }
}

// ============================================================================
// launch
// ============================================================================
extern "C" void kernel_launch(void* const* d_in, const int* in_sizes, int n_in,
                              void* d_out, int out_size)
{
    const float* x  = (const float*)d_in[0];
    const float* Wz = (const float*)d_in[1];
    const float* bz = (const float*)d_in[2];
    const float* Wh = (const float*)d_in[3];
    const float* bh = (const float*)d_in[4];
    float* out = (float*)d_out;

    __half *Xh, *X2, *Wc;
    int *st, *rc;
    float2* ag;
    cudaGetSymbolAddress((void**)&Xh, g_Xh);
    cudaGetSymbolAddress((void**)&X2, g_X2);
    cudaGetSymbolAddress((void**)&Wc, g_Wc);
    cudaGetSymbolAddress((void**)&st, g_status);
    cudaGetSymbolAddress((void**)&ag, g_agg);
    cudaGetSymbolAddress((void**)&rc, g_rowcnt);

    cudaFuncSetAttribute(gemm_fused_kernel,
                         cudaFuncAttributeMaxDynamicSharedMemorySize, GEMM_SMEM);

    // prep: 524288 X-groups + 65536 W-groups = 589824 items -> 2304 blocks
    prep_kernel<<<2304, 256>>>((const float4*)x, (const float4*)Wz,
                               (const float4*)Wh, (uint4*)Xh, (uint4*)Wc, st, rc);

    gemm_fused_kernel<<<4096, NT, GEMM_SMEM>>>(
        Xh, X2, Wc, bz, bh, st, ag, rc, X2, out);
}